// round 11
// baseline (speedup 1.0000x reference)
// O3onO2 tensor product — fp32 SIMT, f32x2 FMAs, TILE_M=32, 2 CTAs/SM.
// v11: li>=2 combine reads x from a coalesced smem stage (k split in halves),
// bank-conflict-free strided LDS (odd row stride) + STS.64 z writes.
// li<2 keep direct-global combine. GEMM/W-stage/epilogue = proven v6 code.
#include <cuda_runtime.h>
#include <cstdint>

#define NROWS    65536
#define TILE_M   32
#define NTHREADS 256
#define W_STRIDE 66
#define Z_STRIDE 34
#define W_OFF    0
#define X_OFF    4224                       // 64*66 W floats
#define ZB_OFF   (X_OFF + 7200)            // x-stage region: 32*225 max
#define SMEM_FLOATS (ZB_OFF + 7616)        // z region: 32*7*34 max -> 19040
#define SMEM_BYTES  (SMEM_FLOATS * 4)      // 76160 B -> 2 CTAs/SM

__device__ __forceinline__ constexpr int blk_off(int l) {
    return l == 0 ? 0 : (l == 1 ? 64 : (l == 2 ? 256 : 576));
}

__device__ __forceinline__ unsigned long long pack2(float a, float b) {
    unsigned long long r;
    asm("mov.b64 %0, {%1, %2};" : "=l"(r) : "f"(a), "f"(b));
    return r;
}
__device__ __forceinline__ unsigned long long dup2(float a) {
    unsigned long long r;
    asm("mov.b64 %0, {%1, %1};" : "=l"(r) : "f"(a));
    return r;
}
__device__ __forceinline__ void fma2(unsigned long long& d,
                                     unsigned long long a,
                                     unsigned long long b) {
    asm("fma.rn.f32x2 %0, %1, %2, %0;" : "+l"(d) : "l"(a), "l"(b));
}

// ---- stage W transposed: ws[i*66 + o] = W[o][i] (2-way STS, coalesced LDG)
template <int LO, int LI>
__device__ __forceinline__ void stage_w(float* __restrict__ sm,
                                        const float* __restrict__ wts) {
    const float* gw = wts + (LO * 4 + LI) * 4096;
    const int tid = threadIdx.x;
#pragma unroll
    for (int s = 0; s < 16; s++) {
        const int idx = tid + s * NTHREADS;
        const int o = idx >> 6, i = idx & 63;
        sm[W_OFF + i * W_STRIDE + o] = __ldg(gw + idx);
    }
}

// ---- direct combine (li = 0,1): v6 code ----
template <int LO, int LI>
__device__ __forceinline__ void combine_direct(
    float* __restrict__ sm, const float* __restrict__ gx,
    const float* __restrict__ hz, const float* __restrict__ hpg,
    const float* __restrict__ hng)
{
    constexpr int W21 = 2 * LI + 1;
    constexpr int MM  = LO < LI ? LO : LI;
    constexpr int NZ  = 2 * MM + 1;
    constexpr int P   = LO * 4 + LI;
    const int tid = threadIdx.x;
    const float h0 = __ldg(hz + P);
    float hp[MM ? MM : 1], hn[MM ? MM : 1];
#pragma unroll
    for (int m = 0; m < MM; m++) {
        hp[m] = __ldg(hpg + P * 3 + m);
        hn[m] = __ldg(hng + P * 3 + m);
    }
    float* zs = sm + ZB_OFF;
#pragma unroll
    for (int s = 0; s < (64 * TILE_M) / NTHREADS; s++) {
        const int it = tid + s * NTHREADS;
        const int k = it & 63;
        const int r = it >> 6;
        const float* xb = gx + (size_t)r * 1024 + k * W21 + LI;
        float* zcol = zs + (k * NZ) * Z_STRIDE + r;
        zcol[0] = h0 * __ldg(xb);
#pragma unroll
        for (int m = 1; m <= MM; m++) {
            const float xp = __ldg(xb + m);
            const float xn = __ldg(xb - m);
            zcol[(2 * m - 1) * Z_STRIDE] = hp[m - 1] * xp + hn[m - 1] * xn;
            zcol[(2 * m) * Z_STRIDE]     = hp[m - 1] * xn - hn[m - 1] * xp;
        }
    }
}

// ---- staged path (li = 2,3): coalesced x half-stage ----
template <int LI>
__device__ __forceinline__ void stage_x(float* __restrict__ sm,
                                        const float* __restrict__ gx, int h) {
    constexpr int W21 = 2 * LI + 1;
    constexpr int XH  = 32 * W21;           // half width in floats
    constexpr int XST = XH + 1;             // odd row stride
    const float* gsrc = gx + h * XH;
    float* xs = sm + X_OFF;
    const int tid = threadIdx.x;
#pragma unroll
    for (int s = 0; s < (TILE_M * XH) / NTHREADS; s++) {
        const int idx = tid + s * NTHREADS;
        const int r = idx / XH;
        const int j = idx - r * XH;
        xs[r * XST + j] = __ldg(gsrc + (size_t)r * 1024 + j);
    }
}

template <int LO, int LI>
__device__ __forceinline__ void combine_staged(
    float* __restrict__ sm, const float* __restrict__ hz,
    const float* __restrict__ hpg, const float* __restrict__ hng)
{
    constexpr int W21 = 2 * LI + 1;
    constexpr int XST = 32 * W21 + 1;
    constexpr int MM  = LO < LI ? LO : LI;
    constexpr int NZ  = 2 * MM + 1;
    constexpr int P   = LO * 4 + LI;
    const int tid = threadIdx.x;
    const float h0 = __ldg(hz + P);
    float hp[MM ? MM : 1], hn[MM ? MM : 1];
#pragma unroll
    for (int m = 0; m < MM; m++) {
        hp[m] = __ldg(hpg + P * 3 + m);
        hn[m] = __ldg(hng + P * 3 + m);
    }
    const float* xs = sm + X_OFF;
    unsigned long long* zb =
        reinterpret_cast<unsigned long long*>(sm + ZB_OFF);
#pragma unroll
    for (int s = 0; s < 2; s++) {            // 32 k * 16 rp / 256
        const int it = tid + s * NTHREADS;
        const int rp = it & 15;
        const int kk = it >> 4;              // local k 0..31
        const float* b0 = xs + (2 * rp) * XST + kk * W21 + LI;
        const float* b1 = b0 + XST;
        unsigned long long* zc = zb + (kk * NZ) * (Z_STRIDE / 2) + rp;
        zc[0] = pack2(h0 * b0[0], h0 * b1[0]);
#pragma unroll
        for (int m = 1; m <= MM; m++) {
            const float xp0 = b0[m], xn0 = b0[-m];
            const float xp1 = b1[m], xn1 = b1[-m];
            zc[(2 * m - 1) * (Z_STRIDE / 2)] =
                pack2(hp[m - 1] * xp0 + hn[m - 1] * xn0,
                      hp[m - 1] * xp1 + hn[m - 1] * xn1);
            zc[(2 * m) * (Z_STRIDE / 2)] =
                pack2(hp[m - 1] * xn0 - hn[m - 1] * xp0,
                      hp[m - 1] * xn1 - hn[m - 1] * xp1);
        }
    }
}

// ---- GEMM (v6): warp rg = row pairs rg, rg+8; lane og = 2 out channels ----
template <int LO, int LI, int KH>
__device__ __forceinline__ void gemm(
    const float* __restrict__ sm,
    unsigned long long (&acc)[2][2][2 * LO + 1], int rg, int og, int kbase)
{
    constexpr int MM = LO < LI ? LO : LI;
    constexpr int NZ = 2 * MM + 1;
    const unsigned long long* zb =
        reinterpret_cast<const unsigned long long*>(sm + ZB_OFF);
    const float* wsl = sm + W_OFF + og * 2 + kbase * W_STRIDE;
#pragma unroll 4
    for (int k = 0; k < KH; k++) {
        const float2 wv = *reinterpret_cast<const float2*>(wsl + k * W_STRIDE);
        const unsigned long long w0 = dup2(wv.x);
        const unsigned long long w1 = dup2(wv.y);
#pragma unroll
        for (int zc = 0; zc < NZ; zc++) {
            const int c = (zc == 0) ? LO
                         : ((zc & 1) ? LO + (zc + 1) / 2 : LO - zc / 2);
            const int col = k * NZ + zc;
            const unsigned long long zA = zb[col * (Z_STRIDE / 2) + rg];
            const unsigned long long zB = zb[col * (Z_STRIDE / 2) + rg + 8];
            fma2(acc[0][0][c], zA, w0);
            fma2(acc[0][1][c], zA, w1);
            fma2(acc[1][0][c], zB, w0);
            fma2(acc[1][1][c], zB, w1);
        }
    }
}

template <int LO>
__device__ __forceinline__ void run(
    float* __restrict__ sm, const float* __restrict__ x,
    const float* __restrict__ wts, const float* __restrict__ hz,
    const float* __restrict__ hpg, const float* __restrict__ hng,
    float* __restrict__ out, int tile)
{
    constexpr int NC  = 2 * LO + 1;
    constexpr int SEG = 64 * NC;
    constexpr int NQ  = SEG / 4;
    const int tid = threadIdx.x;
    const int rg  = tid >> 5;
    const int og  = tid & 31;
    const float* gx = x + (size_t)tile * TILE_M * 1024;

    unsigned long long acc[2][2][NC];
#pragma unroll
    for (int a = 0; a < 2; a++)
#pragma unroll
        for (int b = 0; b < 2; b++)
#pragma unroll
            for (int c = 0; c < NC; c++) acc[a][b][c] = 0ull;

    // li = 0, 1: direct combine
    stage_w<LO, 0>(sm, wts);
    combine_direct<LO, 0>(sm, gx + blk_off(0), hz, hpg, hng);
    __syncthreads();
    gemm<LO, 0, 64>(sm, acc, rg, og, 0);
    __syncthreads();
    stage_w<LO, 1>(sm, wts);
    combine_direct<LO, 1>(sm, gx + blk_off(1), hz, hpg, hng);
    __syncthreads();
    gemm<LO, 1, 64>(sm, acc, rg, og, 0);

    // li = 2: staged halves
    __syncthreads();
    stage_w<LO, 2>(sm, wts);
    stage_x<2>(sm, gx + blk_off(2), 0);
    __syncthreads();
    combine_staged<LO, 2>(sm, hz, hpg, hng);
    __syncthreads();
    gemm<LO, 2, 32>(sm, acc, rg, og, 0);
    stage_x<2>(sm, gx + blk_off(2), 1);
    __syncthreads();
    combine_staged<LO, 2>(sm, hz, hpg, hng);
    __syncthreads();
    gemm<LO, 2, 32>(sm, acc, rg, og, 32);

    // li = 3: staged halves
    __syncthreads();
    stage_w<LO, 3>(sm, wts);
    stage_x<3>(sm, gx + blk_off(3), 0);
    __syncthreads();
    combine_staged<LO, 3>(sm, hz, hpg, hng);
    __syncthreads();
    gemm<LO, 3, 32>(sm, acc, rg, og, 0);
    stage_x<3>(sm, gx + blk_off(3), 1);
    __syncthreads();
    combine_staged<LO, 3>(sm, hz, hpg, hng);
    __syncthreads();
    gemm<LO, 3, 32>(sm, acc, rg, og, 32);

    // ---- output: stage tile in smem (global layout), coalesced f4 stores ----
    __syncthreads();                      // everyone done reading z
    float* smo = sm + X_OFF;
#pragma unroll
    for (int pr = 0; pr < 2; pr++) {
        const int rbase = 2 * (rg + pr * 8);
#pragma unroll
        for (int oo = 0; oo < 2; oo++) {
            const int o = og * 2 + oo;
#pragma unroll
            for (int c = 0; c < NC; c++) {
                const unsigned long long v = acc[pr][oo][c];
                smo[rbase * SEG + o * NC + c] =
                    __uint_as_float((unsigned)(v & 0xffffffffu));
                smo[(rbase + 1) * SEG + o * NC + c] =
                    __uint_as_float((unsigned)(v >> 32));
            }
        }
    }
    __syncthreads();
    float* go = out + (size_t)tile * TILE_M * 1024 + blk_off(LO);
#pragma unroll
    for (int rr = 0; rr < TILE_M / 8; rr++) {
        const int r = rg * (TILE_M / 8) + rr;
        for (int j = og; j < NQ; j += 32) {
            *reinterpret_cast<float4*>(go + (size_t)r * 1024 + j * 4) =
                *reinterpret_cast<const float4*>(smo + r * SEG + j * 4);
        }
    }
}

extern "C" __global__ void __launch_bounds__(NTHREADS, 2)
tp_kernel(const float* __restrict__ x, const float* __restrict__ wts,
          const float* __restrict__ hz, const float* __restrict__ hpg,
          const float* __restrict__ hng, float* __restrict__ out)
{
    extern __shared__ float sm[];
    const int tile = blockIdx.y;
    switch (blockIdx.x) {
        case 0: run<0>(sm, x, wts, hz, hpg, hng, out, tile); break;
        case 1: run<1>(sm, x, wts, hz, hpg, hng, out, tile); break;
        case 2: run<2>(sm, x, wts, hz, hpg, hng, out, tile); break;
        default: run<3>(sm, x, wts, hz, hpg, hng, out, tile); break;
    }
}

extern "C" void kernel_launch(void* const* d_in, const int* in_sizes, int n_in,
                              void* d_out, int out_size)
{
    const float* x   = (const float*)d_in[0];
    const float* wts = (const float*)d_in[1];
    const float* hz  = (const float*)d_in[2];
    const float* hpg = (const float*)d_in[3];
    const float* hng = (const float*)d_in[4];
    float* out = (float*)d_out;

    cudaFuncSetAttribute(tp_kernel, cudaFuncAttributeMaxDynamicSharedMemorySize,
                         SMEM_BYTES);
    dim3 grid(4, NROWS / TILE_M);
    tp_kernel<<<grid, NTHREADS, SMEM_BYTES>>>(x, wts, hz, hpg, hng, out);
}

// round 12
// speedup vs baseline: 1.0856x; 1.0856x over previous
// O3onO2 tensor product — fp32 SIMT, f32x2 FMAs, TILE_M=32, 2 CTAs/SM.
// v12: cp.async double-buffered x prefetch (8 k-half chunks); combine reads
// smem (conflict-free, odd lane stride); GEMM/W-stage/epilogue = proven v6.
#include <cuda_runtime.h>
#include <cstdint>

#define NROWS    65536
#define TILE_M   32
#define NTHREADS 256
#define W_STRIDE 66
#define Z_STRIDE 34
#define WT_OFF   0
#define Z_OFF    4224                        // 64*66 W floats
#define XB0_OFF  (Z_OFF + 7616)             // z: 32k * 7 * 34 = 7616 floats
#define XB1_OFF  (XB0_OFF + 7168)           // xb: 32 rows * 224 floats max
#define SMEM_FLOATS (XB1_OFF + 7168)        // 26176
#define SMEM_BYTES  (SMEM_FLOATS * 4)       // 104704 B -> 2 CTAs/SM

__device__ __forceinline__ constexpr int blk_off(int l) {
    return l == 0 ? 0 : (l == 1 ? 64 : (l == 2 ? 256 : 576));
}

__device__ __forceinline__ unsigned long long dup2(float a) {
    unsigned long long r;
    asm("mov.b64 %0, {%1, %1};" : "=l"(r) : "f"(a));
    return r;
}
__device__ __forceinline__ void fma2(unsigned long long& d,
                                     unsigned long long a,
                                     unsigned long long b) {
    asm("fma.rn.f32x2 %0, %1, %2, %0;" : "+l"(d) : "l"(a), "l"(b));
}

__device__ __forceinline__ uint32_t smem_u32(const void* p) {
    uint32_t a;
    asm("{ .reg .u64 t; cvta.to.shared.u64 t, %1; cvt.u32.u64 %0, t; }"
        : "=r"(a) : "l"(p));
    return a;
}
__device__ __forceinline__ void cp16(uint32_t dst, const float* src) {
    asm volatile("cp.async.cg.shared.global [%0], [%1], 16;"
                 :: "r"(dst), "l"(src));
}
__device__ __forceinline__ void cp_commit() {
    asm volatile("cp.async.commit_group;");
}
__device__ __forceinline__ void cp_wait1() {
    asm volatile("cp.async.wait_group 1;" ::: "memory");
}

// ---- async prefetch of one x chunk: 32 rows x (32*W21) floats, dense ----
template <int LI>
__device__ __forceinline__ void prefetch_x(uint32_t xb_addr,
                                           const float* __restrict__ gsrc) {
    constexpr int W21  = 2 * LI + 1;
    constexpr int ROW16 = 8 * W21;          // 16B units per row
    const int tid = threadIdx.x;
#pragma unroll
    for (int s = 0; s < W21; s++) {         // W21 ops per thread covers all
        const int idx = tid + s * NTHREADS;
        const int r = idx / ROW16;
        const int u = idx - r * ROW16;
        cp16(xb_addr + idx * 16, gsrc + (size_t)r * 1024 + u * 4);
    }
}

// ---- stage W transposed (v6): ws[i*66 + o] = W[o][i] ----
template <int LO, int LI>
__device__ __forceinline__ void stage_w(float* __restrict__ sm,
                                        const float* __restrict__ wts) {
    const float* gw = wts + (LO * 4 + LI) * 4096;
    const int tid = threadIdx.x;
#pragma unroll
    for (int s = 0; s < 16; s++) {
        const int idx = tid + s * NTHREADS;
        const int o = idx >> 6, i = idx & 63;
        sm[WT_OFF + i * W_STRIDE + o] = __ldg(gw + idx);
    }
}

// ---- combine from smem x chunk -> z (32 local k cols) ----
template <int LO, int LI>
__device__ __forceinline__ void combine_s(
    float* __restrict__ sm, const float* __restrict__ xbuf,
    const float* __restrict__ hz, const float* __restrict__ hpg,
    const float* __restrict__ hng)
{
    constexpr int W21 = 2 * LI + 1;
    constexpr int XST = 32 * W21;           // dense row stride
    constexpr int MM  = LO < LI ? LO : LI;
    constexpr int NZ  = 2 * MM + 1;
    constexpr int P   = LO * 4 + LI;
    const int tid = threadIdx.x;
    const float h0 = __ldg(hz + P);
    float hp[MM ? MM : 1], hn[MM ? MM : 1];
#pragma unroll
    for (int m = 0; m < MM; m++) {
        hp[m] = __ldg(hpg + P * 3 + m);
        hn[m] = __ldg(hng + P * 3 + m);
    }
    float* zs = sm + Z_OFF;
#pragma unroll
    for (int s = 0; s < 4; s++) {           // 32 k * 32 r / 256
        const int it = tid + s * NTHREADS;
        const int kk = it & 31;             // lane -> odd stride W21: no bank cf
        const int r  = it >> 5;
        const float* xb = xbuf + r * XST + kk * W21 + LI;
        float* zcol = zs + (kk * NZ) * Z_STRIDE + r;
        zcol[0] = h0 * xb[0];
#pragma unroll
        for (int m = 1; m <= MM; m++) {
            const float xp = xb[m];
            const float xn = xb[-m];
            zcol[(2 * m - 1) * Z_STRIDE] = hp[m - 1] * xp + hn[m - 1] * xn;
            zcol[(2 * m) * Z_STRIDE]     = hp[m - 1] * xn - hn[m - 1] * xp;
        }
    }
}

// ---- GEMM (v6): warp rg = row pairs rg, rg+8; lane og = 2 out channels ----
template <int LO, int LI>
__device__ __forceinline__ void gemm(
    const float* __restrict__ sm,
    unsigned long long (&acc)[2][2][2 * LO + 1], int rg, int og, int kbase)
{
    constexpr int MM = LO < LI ? LO : LI;
    constexpr int NZ = 2 * MM + 1;
    const unsigned long long* zb =
        reinterpret_cast<const unsigned long long*>(sm + Z_OFF);
    const float* wsl = sm + WT_OFF + og * 2 + kbase * W_STRIDE;
#pragma unroll 4
    for (int k = 0; k < 32; k++) {
        const float2 wv = *reinterpret_cast<const float2*>(wsl + k * W_STRIDE);
        const unsigned long long w0 = dup2(wv.x);
        const unsigned long long w1 = dup2(wv.y);
#pragma unroll
        for (int zc = 0; zc < NZ; zc++) {
            const int c = (zc == 0) ? LO
                         : ((zc & 1) ? LO + (zc + 1) / 2 : LO - zc / 2);
            const int col = k * NZ + zc;
            const unsigned long long zA = zb[col * (Z_STRIDE / 2) + rg];
            const unsigned long long zB = zb[col * (Z_STRIDE / 2) + rg + 8];
            fma2(acc[0][0][c], zA, w0);
            fma2(acc[0][1][c], zA, w1);
            fma2(acc[1][0][c], zB, w0);
            fma2(acc[1][1][c], zB, w1);
        }
    }
}

template <int LO>
__device__ __forceinline__ void run(
    float* __restrict__ sm, const float* __restrict__ x,
    const float* __restrict__ wts, const float* __restrict__ hz,
    const float* __restrict__ hpg, const float* __restrict__ hng,
    float* __restrict__ out, int tile)
{
    constexpr int NC  = 2 * LO + 1;
    constexpr int SEG = 64 * NC;
    constexpr int NQ  = SEG / 4;
    const int tid = threadIdx.x;
    const int rg  = tid >> 5;
    const int og  = tid & 31;
    const float* gx = x + (size_t)tile * TILE_M * 1024;
    float* xb0 = sm + XB0_OFF;
    float* xb1 = sm + XB1_OFF;
    const uint32_t xb0a = smem_u32(xb0);
    const uint32_t xb1a = smem_u32(xb1);

    unsigned long long acc[2][2][NC];
#pragma unroll
    for (int a = 0; a < 2; a++)
#pragma unroll
        for (int b = 0; b < 2; b++)
#pragma unroll
            for (int c = 0; c < NC; c++) acc[a][b][c] = 0ull;

    const float* g0 = gx + blk_off(0);
    const float* g1 = gx + blk_off(1);
    const float* g2 = gx + blk_off(2);
    const float* g3 = gx + blk_off(3);

    // prologue: chunks 0 (li0 h0) and 1 (li0 h1)
    prefetch_x<0>(xb0a, g0);        cp_commit();
    prefetch_x<0>(xb1a, g0 + 32);   cp_commit();

    // chunk 0: li0 h0 | prefetch chunk 2 = li1 h0
    cp_wait1(); __syncthreads();
    stage_w<LO, 0>(sm, wts);
    combine_s<LO, 0>(sm, xb0, hz, hpg, hng);
    __syncthreads();
    prefetch_x<1>(xb0a, g1);        cp_commit();
    gemm<LO, 0>(sm, acc, rg, og, 0);

    // chunk 1: li0 h1 | prefetch chunk 3 = li1 h1
    cp_wait1(); __syncthreads();
    combine_s<LO, 0>(sm, xb1, hz, hpg, hng);
    __syncthreads();
    prefetch_x<1>(xb1a, g1 + 96);   cp_commit();
    gemm<LO, 0>(sm, acc, rg, og, 32);

    // chunk 2: li1 h0 | prefetch chunk 4 = li2 h0
    cp_wait1(); __syncthreads();
    stage_w<LO, 1>(sm, wts);
    combine_s<LO, 1>(sm, xb0, hz, hpg, hng);
    __syncthreads();
    prefetch_x<2>(xb0a, g2);        cp_commit();
    gemm<LO, 1>(sm, acc, rg, og, 0);

    // chunk 3: li1 h1 | prefetch chunk 5 = li2 h1
    cp_wait1(); __syncthreads();
    combine_s<LO, 1>(sm, xb1, hz, hpg, hng);
    __syncthreads();
    prefetch_x<2>(xb1a, g2 + 160);  cp_commit();
    gemm<LO, 1>(sm, acc, rg, og, 32);

    // chunk 4: li2 h0 | prefetch chunk 6 = li3 h0
    cp_wait1(); __syncthreads();
    stage_w<LO, 2>(sm, wts);
    combine_s<LO, 2>(sm, xb0, hz, hpg, hng);
    __syncthreads();
    prefetch_x<3>(xb0a, g3);        cp_commit();
    gemm<LO, 2>(sm, acc, rg, og, 0);

    // chunk 5: li2 h1 | prefetch chunk 7 = li3 h1
    cp_wait1(); __syncthreads();
    combine_s<LO, 2>(sm, xb1, hz, hpg, hng);
    __syncthreads();
    prefetch_x<3>(xb1a, g3 + 224);  cp_commit();
    gemm<LO, 2>(sm, acc, rg, og, 32);

    // chunk 6: li3 h0
    cp_wait1(); __syncthreads();
    stage_w<LO, 3>(sm, wts);
    combine_s<LO, 3>(sm, xb0, hz, hpg, hng);
    __syncthreads();
    cp_commit();                    // empty group keeps wait math uniform
    gemm<LO, 3>(sm, acc, rg, og, 0);

    // chunk 7: li3 h1
    cp_wait1(); __syncthreads();
    combine_s<LO, 3>(sm, xb1, hz, hpg, hng);
    __syncthreads();
    gemm<LO, 3>(sm, acc, rg, og, 32);

    // ---- output: stage tile in smem (global layout), coalesced f4 stores ----
    __syncthreads();                      // everyone done reading z
    float* smo = sm + Z_OFF;              // 14784 floats available >= 14336
#pragma unroll
    for (int pr = 0; pr < 2; pr++) {
        const int rbase = 2 * (rg + pr * 8);
#pragma unroll
        for (int oo = 0; oo < 2; oo++) {
            const int o = og * 2 + oo;
#pragma unroll
            for (int c = 0; c < NC; c++) {
                const unsigned long long v = acc[pr][oo][c];
                smo[rbase * SEG + o * NC + c] =
                    __uint_as_float((unsigned)(v & 0xffffffffu));
                smo[(rbase + 1) * SEG + o * NC + c] =
                    __uint_as_float((unsigned)(v >> 32));
            }
        }
    }
    __syncthreads();
    float* go = out + (size_t)tile * TILE_M * 1024 + blk_off(LO);
#pragma unroll
    for (int rr = 0; rr < TILE_M / 8; rr++) {
        const int r = rg * (TILE_M / 8) + rr;
        for (int j = og; j < NQ; j += 32) {
            *reinterpret_cast<float4*>(go + (size_t)r * 1024 + j * 4) =
                *reinterpret_cast<const float4*>(smo + r * SEG + j * 4);
        }
    }
}

extern "C" __global__ void __launch_bounds__(NTHREADS, 2)
tp_kernel(const float* __restrict__ x, const float* __restrict__ wts,
          const float* __restrict__ hz, const float* __restrict__ hpg,
          const float* __restrict__ hng, float* __restrict__ out)
{
    extern __shared__ float sm[];
    const int tile = blockIdx.y;
    switch (blockIdx.x) {
        case 0: run<0>(sm, x, wts, hz, hpg, hng, out, tile); break;
        case 1: run<1>(sm, x, wts, hz, hpg, hng, out, tile); break;
        case 2: run<2>(sm, x, wts, hz, hpg, hng, out, tile); break;
        default: run<3>(sm, x, wts, hz, hpg, hng, out, tile); break;
    }
}

extern "C" void kernel_launch(void* const* d_in, const int* in_sizes, int n_in,
                              void* d_out, int out_size)
{
    const float* x   = (const float*)d_in[0];
    const float* wts = (const float*)d_in[1];
    const float* hz  = (const float*)d_in[2];
    const float* hpg = (const float*)d_in[3];
    const float* hng = (const float*)d_in[4];
    float* out = (float*)d_out;

    cudaFuncSetAttribute(tp_kernel, cudaFuncAttributeMaxDynamicSharedMemorySize,
                         SMEM_BYTES);
    dim3 grid(4, NROWS / TILE_M);
    tp_kernel<<<grid, NTHREADS, SMEM_BYTES>>>(x, wts, hz, hpg, hng, out);
}